// round 2
// baseline (speedup 1.0000x reference)
#include <cuda_runtime.h>
#include <math.h>

#define NSTEP 256
#define G 4
#define NCTA 128
#define NTHREADS 256

// W1 re-tiled: [m(20)][q(33)][j(64)][kk(4)]; k=q*4+kk, zero-pad k>=129
#define W1V_ELEMS (20*33*64*4)
__device__ float g_W1v[W1V_ELEMS];

// ---- shared memory layout (float offsets) ----
#define RING_OFF  0        // [4][20][132]
#define WHH_OFF   10560    // [16 h'][8c*64gate]
#define WAIH_OFF  18752    // [2][16 k][64 gate]
#define WAHH_OFF  20800
#define W2S_OFF   22848    // [16][65]
#define WIH_OFF   23888    // [8*64]
#define BE_OFF    24400    // b_ih+b_hh
#define PS_OFF    24912    // [4 chunk][64 j][4 g]
#define E1S_OFF   25936    // [4][64]
#define ZBUF_OFF  26192    // [4][64] (reused as gate logits)
#define NC_OFF    26448    // [4][128]
#define B1S_OFF   26960
#define BAC_OFF   27024    // [2][64]
#define WGS_OFF   27152    // [8][16]
#define WOS_OFF   27280    // [8][16]
#define EHS_OFF   27408    // [4][16]
#define ECS_OFF   27472
#define AHS_OFF   27536    // [2][4][16]
#define ACS_OFF   27664
#define AIS_OFF   27792    // [4][16]
#define GSM_OFF   27856    // [4][8]
#define OSM_OFF   27888    // [4][8]
#define ERRH_OFF  27920    // [4][10]
#define B2S_OFF   27960
#define BGS_OFF   27976
#define BOS_OFF   27984
#define XS_OFF    27992
#define PRED_OFF  28000
#define THETA_OFF 28004
#define SMEM_FLOATS 28008
#define SMEM_BYTES  (SMEM_FLOATS * 4)

__device__ __forceinline__ float sigf(float v) {
    return __fdividef(1.0f, 1.0f + __expf(-v));
}

__global__ void build_w1v(const float* __restrict__ W1) {
    int idx = blockIdx.x * 256 + threadIdx.x;
    if (idx >= W1V_ELEMS) return;
    int kk = idx & 3;
    int f4 = idx >> 2;
    int j  = f4 & 63;
    int mq = f4 >> 6;
    int m  = mq / 33;
    int q  = mq - m * 33;
    int k  = q * 4 + kk;
    g_W1v[idx] = (k < 129) ? W1[j * 2580 + m * 129 + k] : 0.0f;
}

__global__ __launch_bounds__(NTHREADS, 1)
void mmoe_main(
    const float* __restrict__ x,      const float* __restrict__ pred0,
    const float* __restrict__ gate0,
    const float* __restrict__ W_ih,   const float* __restrict__ W_hh,
    const float* __restrict__ b_ih,   const float* __restrict__ b_hh,
    const float* __restrict__ W_o,    const float* __restrict__ b_o,
    const float* __restrict__ b1,
    const float* __restrict__ W2,     const float* __restrict__ b2,
    const float* __restrict__ Wg,     const float* __restrict__ bg,
    const float* __restrict__ Wa_ih,  const float* __restrict__ Wa_hh,
    const float* __restrict__ ba_ih,  const float* __restrict__ ba_hh,
    float* __restrict__ out)
{
    extern __shared__ float sm[];
    const int tid = threadIdx.x;
    const int b0  = blockIdx.x * G;

    // ---------- init shared ----------
    for (int i = tid; i < 10560; i += NTHREADS) {
        int pos = i % 132;
        sm[RING_OFF + i] = (pos == 128) ? 0.5f : 0.0f;
    }
    for (int i = tid; i < 8192; i += NTHREADS) {
        int h = i >> 9, cg = i & 511;
        sm[WHH_OFF + i] = W_hh[cg * 16 + h];
    }
    for (int i = tid; i < 2048; i += NTHREADS) {
        int l = i >> 10, r = i & 1023, k = r >> 6, gate = r & 63;
        sm[WAIH_OFF + i] = Wa_ih[l * 1024 + gate * 16 + k];
        sm[WAHH_OFF + i] = Wa_hh[l * 1024 + gate * 16 + k];
    }
    for (int i = tid; i < 1040; i += NTHREADS) {
        int j2 = i / 65, k = i - j2 * 65;
        sm[W2S_OFF + i] = (k < 64) ? W2[j2 * 64 + k] : 0.0f;
    }
    for (int i = tid; i < 512; i += NTHREADS) {
        sm[WIH_OFF + i] = W_ih[i];
        sm[BE_OFF + i]  = b_ih[i] + b_hh[i];
    }
    if (tid < 128) {
        sm[BAC_OFF + tid] = ba_ih[tid] + ba_hh[tid];
        sm[WGS_OFF + tid] = Wg[tid];
        sm[WOS_OFF + tid] = W_o[tid];
        sm[AHS_OFF + tid] = 0.0f;
        sm[ACS_OFF + tid] = 0.0f;
    }
    if (tid < 64) { sm[B1S_OFF + tid] = b1[tid]; sm[EHS_OFF + tid] = 0.0f; sm[ECS_OFF + tid] = 0.0f; }
    if (tid < 40) sm[ERRH_OFF + tid] = 0.5f;
    if (tid < 32) sm[GSM_OFF + tid] = gate0[b0 * 8 + tid];
    if (tid < 16) sm[B2S_OFF + tid] = b2[tid];
    if (tid < 8)  { sm[BGS_OFF + tid] = bg[tid]; sm[BOS_OFF + tid] = b_o[tid]; }
    if (tid < 4)  sm[PRED_OFF + tid] = pred0[b0 + tid];
    __syncthreads();

    const int j = tid & 63;
    const int chunk = tid >> 6;
    int head = 0;

    for (int t = 0; t < NSTEP; ++t) {
        int nh_slot = head - 1; if (nh_slot < 0) nh_slot = 19;

        // ---- phase 1: input, error ----
        if (tid < 4) {
            float xv = x[(b0 + tid) * NSTEP + t];
            sm[XS_OFF + tid] = xv;
            float e = xv - sm[PRED_OFF + tid];
            sm[ERRH_OFF + tid * 10 + (t % 10)] = e;
            sm[RING_OFF + (tid * 20 + nh_slot) * 132 + 128] = e;
        }
        __syncthreads();

        // ---- phase 2: experts (8 LSTM cells, shared state) ----
        #pragma unroll
        for (int rep = 0; rep < 2; ++rep) {
            int u = tid + (rep << 8);
            int g = u >> 7, c = (u >> 4) & 7, h = u & 15;
            int cg = c << 6;
            float xv = sm[XS_OFF + g];
            float zi = sm[BE_OFF + cg + h]      + xv * sm[WIH_OFF + cg + h];
            float zf = sm[BE_OFF + cg + 16 + h] + xv * sm[WIH_OFF + cg + 16 + h];
            float zg = sm[BE_OFF + cg + 32 + h] + xv * sm[WIH_OFF + cg + 32 + h];
            float zo = sm[BE_OFF + cg + 48 + h] + xv * sm[WIH_OFF + cg + 48 + h];
            #pragma unroll
            for (int k = 0; k < 16; ++k) {
                float ev = sm[EHS_OFF + g * 16 + k];
                const float* wr = &sm[WHH_OFF + k * 512 + cg];
                zi += ev * wr[h];
                zf += ev * wr[16 + h];
                zg += ev * wr[32 + h];
                zo += ev * wr[48 + h];
            }
            float c2 = sigf(zf) * sm[ECS_OFF + g * 16 + h] + sigf(zi) * tanhf(zg);
            float hn = sigf(zo) * tanhf(c2);
            sm[RING_OFF + (g * 20 + nh_slot) * 132 + c * 16 + h] = hn;
            sm[NC_OFF + g * 128 + c * 16 + h] = c2;
        }
        __syncthreads();

        // ---- phase 3: memory-encode GEMM (64 out x 2580, 4 batches) ----
        {
            float a0 = 0.f, a1 = 0.f, a2 = 0.f, a3 = 0.f;
            const float4* __restrict__ wbase = reinterpret_cast<const float4*>(g_W1v);
            const float4* __restrict__ ring4 = reinterpret_cast<const float4*>(sm);
            #pragma unroll 1
            for (int mm = 0; mm < 5; ++mm) {
                int m = chunk * 5 + mm;
                int slot = nh_slot + m; if (slot >= 20) slot -= 20;
                const float4* wp = wbase + (m * 33) * 64 + j;
                const float4* r0 = ring4 + slot * 33;
                const float4* r1 = r0 + 660;
                const float4* r2 = r0 + 1320;
                const float4* r3 = r0 + 1980;
                #pragma unroll
                for (int q = 0; q < 33; ++q) {
                    float4 w = wp[q * 64];
                    float4 v0 = r0[q];
                    a0 += w.x * v0.x + w.y * v0.y + w.z * v0.z + w.w * v0.w;
                    float4 v1 = r1[q];
                    a1 += w.x * v1.x + w.y * v1.y + w.z * v1.z + w.w * v1.w;
                    float4 v2 = r2[q];
                    a2 += w.x * v2.x + w.y * v2.y + w.z * v2.z + w.w * v2.w;
                    float4 v3 = r3[q];
                    a3 += w.x * v3.x + w.y * v3.y + w.z * v3.z + w.w * v3.w;
                }
            }
            float4* ps4 = reinterpret_cast<float4*>(&sm[PS_OFF]);
            ps4[chunk * 64 + j] = make_float4(a0, a1, a2, a3);
        }
        __syncthreads();

        // ---- phase 4: reduce partials + bias + relu ----
        {
            float s = sm[B1S_OFF + j];
            s += sm[PS_OFF + (0 * 64 + j) * 4 + chunk];
            s += sm[PS_OFF + (1 * 64 + j) * 4 + chunk];
            s += sm[PS_OFF + (2 * 64 + j) * 4 + chunk];
            s += sm[PS_OFF + (3 * 64 + j) * 4 + chunk];
            sm[E1S_OFF + chunk * 64 + j] = fmaxf(s, 0.0f);
        }
        __syncthreads();

        // ---- phase 5: MLP layer2 | expert heads | theta ----
        if (tid < 64) {
            int g = tid >> 4, j2 = tid & 15;
            float s = sm[B2S_OFF + j2];
            #pragma unroll
            for (int k = 0; k < 64; ++k)
                s += sm[E1S_OFF + g * 64 + k] * sm[W2S_OFF + j2 * 65 + k];
            sm[AIS_OFF + g * 16 + j2] = fmaxf(s, 0.0f);
        } else if (tid < 96) {
            int u = tid - 64, g = u >> 3, c = u & 7;
            float s = sm[BOS_OFF + c];
            const float* rr = &sm[RING_OFF + (g * 20 + nh_slot) * 132 + c * 16];
            #pragma unroll
            for (int h = 0; h < 16; ++h) s += rr[h] * sm[WOS_OFF + c * 16 + h];
            sm[OSM_OFF + g * 8 + c] = s;
        } else if (tid < 100) {
            int g = tid - 96;
            float s = 0.0f;
            #pragma unroll
            for (int i2 = 0; i2 < 10; ++i2) s += fabsf(sm[ERRH_OFF + g * 10 + i2]);
            sm[THETA_OFF + g] = fminf(0.25f * s, 1.0f);
        }
        __syncthreads();

        // ---- phase 6: agent, 2 stacked LSTM layers ----
        #pragma unroll 1
        for (int l = 0; l < 2; ++l) {
            {
                const float* inp = (l == 0) ? &sm[AIS_OFF + chunk * 16]
                                            : &sm[AHS_OFF + chunk * 16];
                const float* hp  = &sm[AHS_OFF + l * 64 + chunk * 16];
                float z = sm[BAC_OFF + l * 64 + j];
                const float* wi = &sm[WAIH_OFF + l * 1024 + j];
                const float* wh = &sm[WAHH_OFF + l * 1024 + j];
                #pragma unroll
                for (int k = 0; k < 16; ++k)
                    z += inp[k] * wi[k * 64] + hp[k] * wh[k * 64];
                sm[ZBUF_OFF + chunk * 64 + j] = z;
            }
            __syncthreads();
            if (tid < 64) {
                int g2 = tid >> 4, h = tid & 15;
                float zi = sm[ZBUF_OFF + g2 * 64 + h];
                float zf = sm[ZBUF_OFF + g2 * 64 + 16 + h];
                float zg = sm[ZBUF_OFF + g2 * 64 + 32 + h];
                float zo = sm[ZBUF_OFF + g2 * 64 + 48 + h];
                float c2 = sigf(zf) * sm[ACS_OFF + l * 64 + g2 * 16 + h]
                         + sigf(zi) * tanhf(zg);
                float hn = sigf(zo) * tanhf(c2);
                sm[ACS_OFF + l * 64 + g2 * 16 + h] = c2;
                sm[AHS_OFF + l * 64 + g2 * 16 + h] = hn;
            }
            __syncthreads();
        }

        // ---- phase 7a: gate logits (reuse ZBUF) ----
        if (tid < 32) {
            int g = tid >> 3, c = tid & 7;
            float s = sm[BGS_OFF + c];
            const float* a1p = &sm[AHS_OFF + 64 + g * 16];
            #pragma unroll
            for (int k = 0; k < 16; ++k) s += a1p[k] * sm[WGS_OFF + c * 16 + k];
            sm[ZBUF_OFF + g * 8 + c] = s;
        }
        __syncthreads();

        // ---- phase 7b: softmax + theta blend + pred + output ----
        if (tid < 4) {
            int g = tid;
            float mx = -1e30f;
            #pragma unroll
            for (int c = 0; c < 8; ++c) mx = fmaxf(mx, sm[ZBUF_OFF + g * 8 + c]);
            float ex[8], ssum = 0.0f;
            #pragma unroll
            for (int c = 0; c < 8; ++c) { ex[c] = __expf(sm[ZBUF_OFF + g * 8 + c] - mx); ssum += ex[c]; }
            float inv = __fdividef(1.0f, ssum);
            float th = sm[THETA_OFF + g];
            float pred = 0.0f;
            #pragma unroll
            for (int c = 0; c < 8; ++c) {
                float gf = ex[c] * inv * th + sm[GSM_OFF + g * 8 + c] * (1.0f - th);
                sm[GSM_OFF + g * 8 + c] = gf;
                pred += gf * sm[OSM_OFF + g * 8 + c];
            }
            sm[PRED_OFF + g] = pred;
            out[(b0 + g) * NSTEP + t] = pred;
        }
        __syncthreads();

        // ---- phase 7c: eh2 / ec2 ----
        if (tid < 64) {
            int g = tid >> 4, h = tid & 15;
            const float* rr = &sm[RING_OFF + (g * 20 + nh_slot) * 132];
            const float* nc = &sm[NC_OFF + g * 128];
            float se = 0.0f, sc = 0.0f;
            #pragma unroll
            for (int c = 0; c < 8; ++c) {
                float gf = sm[GSM_OFF + g * 8 + c];
                se += gf * rr[c * 16 + h];
                sc += gf * nc[c * 16 + h];
            }
            sm[EHS_OFF + g * 16 + h] = se;
            sm[ECS_OFF + g * 16 + h] = sc;
        }
        __syncthreads();

        head = nh_slot;
    }
}

extern "C" void kernel_launch(void* const* d_in, const int* in_sizes, int n_in,
                              void* d_out, int out_size) {
    const float* x      = (const float*)d_in[0];
    const float* pred0  = (const float*)d_in[1];
    const float* gate0  = (const float*)d_in[2];
    const float* W_ih   = (const float*)d_in[3];
    const float* W_hh   = (const float*)d_in[4];
    const float* b_ih   = (const float*)d_in[5];
    const float* b_hh   = (const float*)d_in[6];
    const float* W_o    = (const float*)d_in[7];
    const float* b_o    = (const float*)d_in[8];
    const float* W1     = (const float*)d_in[9];
    const float* b1     = (const float*)d_in[10];
    const float* W2     = (const float*)d_in[11];
    const float* b2     = (const float*)d_in[12];
    const float* Wg     = (const float*)d_in[13];
    const float* bg     = (const float*)d_in[14];
    const float* Wa_ih  = (const float*)d_in[15];
    const float* Wa_hh  = (const float*)d_in[16];
    const float* ba_ih  = (const float*)d_in[17];
    const float* ba_hh  = (const float*)d_in[18];
    float* out = (float*)d_out;

    cudaFuncSetAttribute(mmoe_main, cudaFuncAttributeMaxDynamicSharedMemorySize, SMEM_BYTES);

    build_w1v<<<(W1V_ELEMS + 255) / 256, 256>>>(W1);
    mmoe_main<<<NCTA, NTHREADS, SMEM_BYTES>>>(
        x, pred0, gate0, W_ih, W_hh, b_ih, b_hh, W_o, b_o,
        b1, W2, b2, Wg, bg, Wa_ih, Wa_hh, ba_ih, ba_hh, out);
}

// round 3
// speedup vs baseline: 1.0222x; 1.0222x over previous
#include <cuda_runtime.h>
#include <math.h>

#define NSTEP 256
#define G 4
#define NCTA 128
#define NTHREADS 512

// W1 re-tiled: [m(20)][q(34)][j(64)][kk(4)]; k=q*4+kk, zero-pad k>=129
#define W1V_ELEMS (20*34*64*4)
__device__ float g_W1v[W1V_ELEMS];

// ---- shared memory layout (float offsets) ----
// ring row padded to 136 floats (34 float4): cols 0..127 = nh, 128 = error, 129..135 = 0
#define RING_OFF  0        // [4][20][136] = 10880
#define WHH_OFF   10880    // [16 h'][8c*64gate] = 8192
#define WAIH_OFF  19072    // [2][16 k][64 gate] = 2048
#define WAHH_OFF  21120    // 2048
#define W2S_OFF   23168    // [16][65] = 1040
#define WIH_OFF   24208    // 512
#define BE_OFF    24720    // 512
#define PS_OFF    25232    // [8 chunk][64 j][4 g] = 2048
#define E1S_OFF   27280    // [4][64]
#define ZBUF_OFF  27536    // [4][64]
#define NC_OFF    27792    // [4][128]
#define B1S_OFF   28304    // 64
#define BAC_OFF   28368    // [2][64]
#define WGS_OFF   28496    // [8][16]
#define WOS_OFF   28624    // [8][16]
#define EHS_OFF   28752    // [4][16]
#define ECS_OFF   28816
#define AHS_OFF   28880    // [2][4][16]
#define ACS_OFF   29008
#define AIS_OFF   29136    // [4][16]
#define GSM_OFF   29200    // [4][8]
#define OSM_OFF   29232    // [4][8]
#define ERRH_OFF  29264    // [4][10]
#define B2S_OFF   29304
#define BGS_OFF   29320
#define BOS_OFF   29328
#define XS_OFF    29336
#define PRED_OFF  29340
#define THETA_OFF 29344
#define SMEM_FLOATS 29348
#define SMEM_BYTES  (SMEM_FLOATS * 4)

__device__ __forceinline__ float sigf(float v) {
    return __fdividef(1.0f, 1.0f + __expf(-v));
}

#define FMA2(acc, a, b) \
    asm("fma.rn.f32x2 %0, %1, %2, %0;" : "+l"(acc) : "l"(a), "l"(b))

__device__ __forceinline__ float pair_sum(unsigned long long v) {
    union { unsigned long long u; float2 f; } cv; cv.u = v;
    return cv.f.x + cv.f.y;
}

__global__ void build_w1v(const float* __restrict__ W1) {
    int idx = blockIdx.x * 256 + threadIdx.x;
    if (idx >= W1V_ELEMS) return;
    int kk = idx & 3;
    int f4 = idx >> 2;
    int j  = f4 & 63;
    int mq = f4 >> 6;
    int m  = mq / 34;
    int q  = mq - m * 34;
    int k  = q * 4 + kk;
    g_W1v[idx] = (k < 129) ? W1[j * 2580 + m * 129 + k] : 0.0f;
}

__global__ __launch_bounds__(NTHREADS, 1)
void mmoe_main(
    const float* __restrict__ x,      const float* __restrict__ pred0,
    const float* __restrict__ gate0,
    const float* __restrict__ W_ih,   const float* __restrict__ W_hh,
    const float* __restrict__ b_ih,   const float* __restrict__ b_hh,
    const float* __restrict__ W_o,    const float* __restrict__ b_o,
    const float* __restrict__ b1,
    const float* __restrict__ W2,     const float* __restrict__ b2,
    const float* __restrict__ Wg,     const float* __restrict__ bg,
    const float* __restrict__ Wa_ih,  const float* __restrict__ Wa_hh,
    const float* __restrict__ ba_ih,  const float* __restrict__ ba_hh,
    float* __restrict__ out)
{
    extern __shared__ float sm[];
    const int tid = threadIdx.x;
    const int b0  = blockIdx.x * G;

    // ---------- init shared ----------
    for (int i = tid; i < 10880; i += NTHREADS) {
        int pos = i % 136;
        sm[RING_OFF + i] = (pos == 128) ? 0.5f : 0.0f;
    }
    for (int i = tid; i < 8192; i += NTHREADS) {
        int h = i >> 9, cg = i & 511;
        sm[WHH_OFF + i] = W_hh[cg * 16 + h];
    }
    for (int i = tid; i < 2048; i += NTHREADS) {
        int l = i >> 10, r = i & 1023, k = r >> 6, gate = r & 63;
        sm[WAIH_OFF + i] = Wa_ih[l * 1024 + gate * 16 + k];
        sm[WAHH_OFF + i] = Wa_hh[l * 1024 + gate * 16 + k];
    }
    for (int i = tid; i < 1040; i += NTHREADS) {
        int j2 = i / 65, k = i - j2 * 65;
        sm[W2S_OFF + i] = (k < 64) ? W2[j2 * 64 + k] : 0.0f;
    }
    if (tid < 512) {
        sm[WIH_OFF + tid] = W_ih[tid];
        sm[BE_OFF + tid]  = b_ih[tid] + b_hh[tid];
    }
    if (tid < 128) {
        sm[BAC_OFF + tid] = ba_ih[tid] + ba_hh[tid];
        sm[WGS_OFF + tid] = Wg[tid];
        sm[WOS_OFF + tid] = W_o[tid];
        sm[AHS_OFF + tid] = 0.0f;
        sm[ACS_OFF + tid] = 0.0f;
    }
    if (tid < 64) { sm[B1S_OFF + tid] = b1[tid]; sm[EHS_OFF + tid] = 0.0f; sm[ECS_OFF + tid] = 0.0f; }
    if (tid < 40) sm[ERRH_OFF + tid] = 0.5f;
    if (tid < 32) sm[GSM_OFF + tid] = gate0[b0 * 8 + tid];
    if (tid < 16) sm[B2S_OFF + tid] = b2[tid];
    if (tid < 8)  { sm[BGS_OFF + tid] = bg[tid]; sm[BOS_OFF + tid] = b_o[tid]; }
    if (tid < 4)  sm[PRED_OFF + tid] = pred0[b0 + tid];
    __syncthreads();

    const int j = tid & 63;
    const int chunk = tid >> 6;     // 0..7
    int head = 0;

    // GEMM start position for this chunk (flattened q-block index p0 = chunk*85)
    const int p0 = chunk * 85;
    const int m0 = p0 / 34;
    const int q0 = p0 - m0 * 34;

    for (int t = 0; t < NSTEP; ++t) {
        int nh_slot = head - 1; if (nh_slot < 0) nh_slot = 19;

        // ---- phase 1: input, error ----
        if (tid < 4) {
            float xv = x[(b0 + tid) * NSTEP + t];
            sm[XS_OFF + tid] = xv;
            float e = xv - sm[PRED_OFF + tid];
            sm[ERRH_OFF + tid * 10 + (t % 10)] = e;
            sm[RING_OFF + (tid * 20 + nh_slot) * 136 + 128] = e;
        }
        __syncthreads();

        // ---- phase 2: experts (8 LSTM cells, shared state), 512 items ----
        {
            int g = tid >> 7, c = (tid >> 4) & 7, h = tid & 15;
            int cg = c << 6;
            float xv = sm[XS_OFF + g];
            float zi = sm[BE_OFF + cg + h]      + xv * sm[WIH_OFF + cg + h];
            float zf = sm[BE_OFF + cg + 16 + h] + xv * sm[WIH_OFF + cg + 16 + h];
            float zg = sm[BE_OFF + cg + 32 + h] + xv * sm[WIH_OFF + cg + 32 + h];
            float zo = sm[BE_OFF + cg + 48 + h] + xv * sm[WIH_OFF + cg + 48 + h];
            #pragma unroll
            for (int k = 0; k < 16; ++k) {
                float ev = sm[EHS_OFF + g * 16 + k];
                const float* wr = &sm[WHH_OFF + k * 512 + cg];
                zi += ev * wr[h];
                zf += ev * wr[16 + h];
                zg += ev * wr[32 + h];
                zo += ev * wr[48 + h];
            }
            float c2 = sigf(zf) * sm[ECS_OFF + g * 16 + h] + sigf(zi) * tanhf(zg);
            float hn = sigf(zo) * tanhf(c2);
            sm[RING_OFF + (g * 20 + nh_slot) * 136 + c * 16 + h] = hn;
            sm[NC_OFF + g * 128 + c * 16 + h] = c2;
        }
        __syncthreads();

        // ---- phase 3: memory-encode GEMM via packed f32x2 FMA ----
        {
            int slot0 = nh_slot + m0; if (slot0 >= 20) slot0 -= 20;
            int pos = slot0 * 34 + q0;            // in 16B units within [0,680)

            unsigned long long accA0 = 0ull, accA1 = 0ull, accA2 = 0ull, accA3 = 0ull;
            unsigned long long accB0 = 0ull, accB1 = 0ull, accB2 = 0ull, accB3 = 0ull;

            const ulonglong2* __restrict__ wp =
                reinterpret_cast<const ulonglong2*>(g_W1v) + p0 * 64 + j;
            const ulonglong2* __restrict__ ring2 =
                reinterpret_cast<const ulonglong2*>(sm);

            #pragma unroll 1
            for (int ii = 0; ii < 17; ++ii) {
                #pragma unroll
                for (int u = 0; u < 5; ++u) {
                    ulonglong2 w = *wp; wp += 64;
                    ulonglong2 v0 = ring2[pos];
                    ulonglong2 v1 = ring2[680 + pos];
                    ulonglong2 v2 = ring2[1360 + pos];
                    ulonglong2 v3 = ring2[2040 + pos];
                    FMA2(accA0, w.x, v0.x); FMA2(accB0, w.y, v0.y);
                    FMA2(accA1, w.x, v1.x); FMA2(accB1, w.y, v1.y);
                    FMA2(accA2, w.x, v2.x); FMA2(accB2, w.y, v2.y);
                    FMA2(accA3, w.x, v3.x); FMA2(accB3, w.y, v3.y);
                    ++pos; if (pos == 680) pos = 0;
                }
            }
            float4* ps4 = reinterpret_cast<float4*>(&sm[PS_OFF]);
            ps4[chunk * 64 + j] = make_float4(
                pair_sum(accA0) + pair_sum(accB0),
                pair_sum(accA1) + pair_sum(accB1),
                pair_sum(accA2) + pair_sum(accB2),
                pair_sum(accA3) + pair_sum(accB3));
        }
        __syncthreads();

        // ---- phase 4: reduce partials + bias + relu ----
        if (tid < 256) {
            int g = tid >> 6, jj = tid & 63;
            float s = sm[B1S_OFF + jj];
            #pragma unroll
            for (int c = 0; c < 8; ++c)
                s += sm[PS_OFF + (c * 64 + jj) * 4 + g];
            sm[E1S_OFF + g * 64 + jj] = fmaxf(s, 0.0f);
        }
        __syncthreads();

        // ---- phase 5: MLP layer2 | expert heads | theta ----
        if (tid < 64) {
            int g = tid >> 4, j2 = tid & 15;
            float s = sm[B2S_OFF + j2];
            #pragma unroll
            for (int k = 0; k < 64; ++k)
                s += sm[E1S_OFF + g * 64 + k] * sm[W2S_OFF + j2 * 65 + k];
            sm[AIS_OFF + g * 16 + j2] = fmaxf(s, 0.0f);
        } else if (tid < 96) {
            int u = tid - 64, g = u >> 3, c = u & 7;
            float s = sm[BOS_OFF + c];
            const float* rr = &sm[RING_OFF + (g * 20 + nh_slot) * 136 + c * 16];
            #pragma unroll
            for (int h = 0; h < 16; ++h) s += rr[h] * sm[WOS_OFF + c * 16 + h];
            sm[OSM_OFF + g * 8 + c] = s;
        } else if (tid < 100) {
            int g = tid - 96;
            float s = 0.0f;
            #pragma unroll
            for (int i2 = 0; i2 < 10; ++i2) s += fabsf(sm[ERRH_OFF + g * 10 + i2]);
            sm[THETA_OFF + g] = fminf(0.25f * s, 1.0f);
        }
        __syncthreads();

        // ---- phase 6: agent, 2 stacked LSTM layers ----
        #pragma unroll 1
        for (int l = 0; l < 2; ++l) {
            if (tid < 256) {
                int g = tid >> 6, gate = tid & 63;
                const float* inp = (l == 0) ? &sm[AIS_OFF + g * 16]
                                            : &sm[AHS_OFF + g * 16];
                const float* hp  = &sm[AHS_OFF + l * 64 + g * 16];
                float z = sm[BAC_OFF + l * 64 + gate];
                const float* wi = &sm[WAIH_OFF + l * 1024 + gate];
                const float* wh = &sm[WAHH_OFF + l * 1024 + gate];
                #pragma unroll
                for (int k = 0; k < 16; ++k)
                    z += inp[k] * wi[k * 64] + hp[k] * wh[k * 64];
                sm[ZBUF_OFF + g * 64 + gate] = z;
            }
            __syncthreads();
            if (tid < 64) {
                int g2 = tid >> 4, h = tid & 15;
                float zi = sm[ZBUF_OFF + g2 * 64 + h];
                float zf = sm[ZBUF_OFF + g2 * 64 + 16 + h];
                float zg = sm[ZBUF_OFF + g2 * 64 + 32 + h];
                float zo = sm[ZBUF_OFF + g2 * 64 + 48 + h];
                float c2 = sigf(zf) * sm[ACS_OFF + l * 64 + g2 * 16 + h]
                         + sigf(zi) * tanhf(zg);
                float hn = sigf(zo) * tanhf(c2);
                sm[ACS_OFF + l * 64 + g2 * 16 + h] = c2;
                sm[AHS_OFF + l * 64 + g2 * 16 + h] = hn;
            }
            __syncthreads();
        }

        // ---- phase 7a: gate logits (reuse ZBUF) ----
        if (tid < 32) {
            int g = tid >> 3, c = tid & 7;
            float s = sm[BGS_OFF + c];
            const float* a1p = &sm[AHS_OFF + 64 + g * 16];
            #pragma unroll
            for (int k = 0; k < 16; ++k) s += a1p[k] * sm[WGS_OFF + c * 16 + k];
            sm[ZBUF_OFF + g * 8 + c] = s;
        }
        __syncthreads();

        // ---- phase 7b: softmax + theta blend + pred + output ----
        if (tid < 4) {
            int g = tid;
            float mx = -1e30f;
            #pragma unroll
            for (int c = 0; c < 8; ++c) mx = fmaxf(mx, sm[ZBUF_OFF + g * 8 + c]);
            float ex[8], ssum = 0.0f;
            #pragma unroll
            for (int c = 0; c < 8; ++c) { ex[c] = __expf(sm[ZBUF_OFF + g * 8 + c] - mx); ssum += ex[c]; }
            float inv = __fdividef(1.0f, ssum);
            float th = sm[THETA_OFF + g];
            float pred = 0.0f;
            #pragma unroll
            for (int c = 0; c < 8; ++c) {
                float gf = ex[c] * inv * th + sm[GSM_OFF + g * 8 + c] * (1.0f - th);
                sm[GSM_OFF + g * 8 + c] = gf;
                pred += gf * sm[OSM_OFF + g * 8 + c];
            }
            sm[PRED_OFF + g] = pred;
            out[(b0 + g) * NSTEP + t] = pred;
        }
        __syncthreads();

        // ---- phase 7c: eh2 / ec2 ----
        if (tid < 64) {
            int g = tid >> 4, h = tid & 15;
            const float* rr = &sm[RING_OFF + (g * 20 + nh_slot) * 136];
            const float* nc = &sm[NC_OFF + g * 128];
            float se = 0.0f, sc = 0.0f;
            #pragma unroll
            for (int c = 0; c < 8; ++c) {
                float gf = sm[GSM_OFF + g * 8 + c];
                se += gf * rr[c * 16 + h];
                sc += gf * nc[c * 16 + h];
            }
            sm[EHS_OFF + g * 16 + h] = se;
            sm[ECS_OFF + g * 16 + h] = sc;
        }
        __syncthreads();

        head = nh_slot;
    }
}

extern "C" void kernel_launch(void* const* d_in, const int* in_sizes, int n_in,
                              void* d_out, int out_size) {
    const float* x      = (const float*)d_in[0];
    const float* pred0  = (const float*)d_in[1];
    const float* gate0  = (const float*)d_in[2];
    const float* W_ih   = (const float*)d_in[3];
    const float* W_hh   = (const float*)d_in[4];
    const float* b_ih   = (const float*)d_in[5];
    const float* b_hh   = (const float*)d_in[6];
    const float* W_o    = (const float*)d_in[7];
    const float* b_o    = (const float*)d_in[8];
    const float* W1     = (const float*)d_in[9];
    const float* b1     = (const float*)d_in[10];
    const float* W2     = (const float*)d_in[11];
    const float* b2     = (const float*)d_in[12];
    const float* Wg     = (const float*)d_in[13];
    const float* bg     = (const float*)d_in[14];
    const float* Wa_ih  = (const float*)d_in[15];
    const float* Wa_hh  = (const float*)d_in[16];
    const float* ba_ih  = (const float*)d_in[17];
    const float* ba_hh  = (const float*)d_in[18];
    float* out = (float*)d_out;

    cudaFuncSetAttribute(mmoe_main, cudaFuncAttributeMaxDynamicSharedMemorySize, SMEM_BYTES);

    build_w1v<<<(W1V_ELEMS + 255) / 256, 256>>>(W1);
    mmoe_main<<<NCTA, NTHREADS, SMEM_BYTES>>>(
        x, pred0, gate0, W_ih, W_hh, b_ih, b_hh, W_o, b_o,
        b1, W2, b2, Wg, bg, Wa_ih, Wa_hh, ba_ih, ba_hh, out);
}

// round 4
// speedup vs baseline: 1.1646x; 1.1393x over previous
#include <cuda_runtime.h>
#include <cuda_fp16.h>
#include <math.h>

#define NSTEP 256
#define G 4
#define NCTA 128
#define NTHREADS 512

// fp16 W1, re-tiled: [(m*18+qq)][j(64)][kkk(8)]; k=qq*8+kkk, pad k>=129 -> 0
#define W1H_UNITS (20*18)
#define W1H_ELEMS (W1H_UNITS*64*8)
__device__ __half g_W1h[W1H_ELEMS];

// ---- shared memory layout (float offsets) ----
// ring row = 144 floats (36 float4): [0..127]=nh, [128]=error, [129..143]=0
#define RING_OFF   0        // [4][20][144] = 11520
#define W1A_OFF    11520    // m=0 weights fp32 [33 q][64 j][4 kk] = 8448
#define WHH_OFF    19968    // [16 h'][8c*64gate] = 8192
#define WAIH_OFF   28160    // [2][16 k][64 gate] = 2048
#define WAHH_OFF   30208    // 2048
#define W2S_OFF    32256    // [16][65] = 1040
#define WIH_OFF    33296    // 512
#define BE_OFF     33808    // 512
#define PSB_OFF    34320    // GEMM-B partials [6 c][64 j][4 g] = 1536
#define OLDPS_OFF  35856    // [2 parity][64 j * 4 g] = 512
#define E1S_OFF    36368    // [4][64]
#define ZBUF_OFF   36624    // [4][64]
#define NC_OFF     36880    // [4][128]
#define B1S_OFF    37392    // 64
#define BAC_OFF    37456    // [2][64]
#define WGS_OFF    37584    // [8][16]
#define WOS_OFF    37712    // [8][16]
#define EHS_OFF    37840    // [4][16]
#define ECS_OFF    37904
#define AHS_OFF    37968    // [2][4][16]
#define ACS_OFF    38096
#define AIS_OFF    38224    // [4][16]
#define GSM_OFF    38288    // [4][8]
#define OSM_OFF    38320    // [4][8]
#define ERRH_OFF   38352    // [4][10]
#define B2S_OFF    38392
#define BGS_OFF    38408
#define BOS_OFF    38416
#define XS_OFF     38424
#define PRED_OFF   38428
#define THETA_OFF  38432
#define SMEM_FLOATS 38436
#define SMEM_BYTES  (SMEM_FLOATS * 4)

__device__ __forceinline__ float sigf(float v) {
    return __fdividef(1.0f, 1.0f + __expf(-v));
}

#define FMA2(acc, a, b) \
    asm("fma.rn.f32x2 %0, %1, %2, %0;" : "+l"(acc) : "l"(a), "l"(b))

__device__ __forceinline__ float pair_sum(unsigned long long v) {
    union { unsigned long long u; float2 f; } cv; cv.u = v;
    return cv.f.x + cv.f.y;
}

__device__ __forceinline__ unsigned long long f2ull(float2 f) {
    union { float2 f; unsigned long long u; } cv; cv.f = f;
    return cv.u;
}

__global__ void build_w1h(const float* __restrict__ W1) {
    int idx = blockIdx.x * 256 + threadIdx.x;
    if (idx >= W1H_ELEMS) return;
    int kkk = idx & 7;
    int f8  = idx >> 3;
    int j   = f8 & 63;
    int mu  = f8 >> 6;          // m*18+qq in [0,360)
    int m   = mu / 18;
    int qq  = mu - m * 18;
    int k   = qq * 8 + kkk;
    g_W1h[idx] = __float2half((k < 129) ? W1[j * 2580 + m * 129 + k] : 0.0f);
}

__global__ __launch_bounds__(NTHREADS, 1)
void mmoe_main(
    const float* __restrict__ x,      const float* __restrict__ pred0,
    const float* __restrict__ gate0,
    const float* __restrict__ W_ih,   const float* __restrict__ W_hh,
    const float* __restrict__ b_ih,   const float* __restrict__ b_hh,
    const float* __restrict__ W_o,    const float* __restrict__ b_o,
    const float* __restrict__ W1,     const float* __restrict__ b1,
    const float* __restrict__ W2,     const float* __restrict__ b2,
    const float* __restrict__ Wg,     const float* __restrict__ bg,
    const float* __restrict__ Wa_ih,  const float* __restrict__ Wa_hh,
    const float* __restrict__ ba_ih,  const float* __restrict__ ba_hh,
    float* __restrict__ out)
{
    extern __shared__ float sm[];
    const int tid = threadIdx.x;
    const int b0  = blockIdx.x * G;

    // ---------- init shared ----------
    for (int i = tid; i < 11520; i += NTHREADS) {
        int pos = i % 144;
        sm[RING_OFF + i] = (pos == 128) ? 0.5f : 0.0f;
    }
    for (int i = tid; i < 8448; i += NTHREADS) {
        int kk = i & 3, jj = (i >> 2) & 63, q = i >> 8;
        int k = q * 4 + kk;
        sm[W1A_OFF + i] = (k < 129) ? W1[jj * 2580 + k] : 0.0f;
    }
    for (int i = tid; i < 8192; i += NTHREADS) {
        int h = i >> 9, cg = i & 511;
        sm[WHH_OFF + i] = W_hh[cg * 16 + h];
    }
    for (int i = tid; i < 2048; i += NTHREADS) {
        int l = i >> 10, r = i & 1023, k = r >> 6, gate = r & 63;
        sm[WAIH_OFF + i] = Wa_ih[l * 1024 + gate * 16 + k];
        sm[WAHH_OFF + i] = Wa_hh[l * 1024 + gate * 16 + k];
    }
    for (int i = tid; i < 1040; i += NTHREADS) {
        int j2 = i / 65, k = i - j2 * 65;
        sm[W2S_OFF + i] = (k < 64) ? W2[j2 * 64 + k] : 0.0f;
    }
    if (tid < 512) {
        sm[WIH_OFF + tid] = W_ih[tid];
        sm[BE_OFF + tid]  = b_ih[tid] + b_hh[tid];
    }
    if (tid < 256) {
        // initial old-rows partial: rows m=1..19 are (0,...,0, 0.5)
        int jj = tid >> 2, gg = tid & 3;
        float sacc = 0.0f;
        for (int m = 1; m < 20; ++m) sacc += W1[jj * 2580 + m * 129 + 128];
        sm[OLDPS_OFF + jj * 4 + gg] = 0.5f * sacc;
    }
    if (tid < 128) {
        sm[BAC_OFF + tid] = ba_ih[tid] + ba_hh[tid];
        sm[WGS_OFF + tid] = Wg[tid];
        sm[WOS_OFF + tid] = W_o[tid];
        sm[AHS_OFF + tid] = 0.0f;
        sm[ACS_OFF + tid] = 0.0f;
    }
    if (tid < 64) { sm[B1S_OFF + tid] = b1[tid]; sm[EHS_OFF + tid] = 0.0f; sm[ECS_OFF + tid] = 0.0f; }
    if (tid < 40) sm[ERRH_OFF + tid] = 0.5f;
    if (tid < 32) sm[GSM_OFF + tid] = gate0[b0 * 8 + tid];
    if (tid < 16) sm[B2S_OFF + tid] = b2[tid];
    if (tid < 8)  { sm[BGS_OFF + tid] = bg[tid]; sm[BOS_OFF + tid] = b_o[tid]; }
    if (tid < 4)  sm[PRED_OFF + tid] = pred0[b0 + tid];
    __syncthreads();

    int head = 0;

    for (int t = 0; t < NSTEP; ++t) {
        int s = head - 1; if (s < 0) s = 19;   // nh_slot

        // ---- phase 1: input, error ----
        if (tid < 4) {
            float xv = x[(b0 + tid) * NSTEP + t];
            sm[XS_OFF + tid] = xv;
            float e = xv - sm[PRED_OFF + tid];
            sm[ERRH_OFF + tid * 10 + (t % 10)] = e;
            sm[RING_OFF + (tid * 20 + s) * 144 + 128] = e;
        }
        __syncthreads();

        // ---- phase 2: experts (all 512 threads) ----
        {
            int g = tid >> 7, c = (tid >> 4) & 7, h = tid & 15;
            int cg = c << 6;
            float xv = sm[XS_OFF + g];
            float zi = sm[BE_OFF + cg + h]      + xv * sm[WIH_OFF + cg + h];
            float zf = sm[BE_OFF + cg + 16 + h] + xv * sm[WIH_OFF + cg + 16 + h];
            float zg = sm[BE_OFF + cg + 32 + h] + xv * sm[WIH_OFF + cg + 32 + h];
            float zo = sm[BE_OFF + cg + 48 + h] + xv * sm[WIH_OFF + cg + 48 + h];
            #pragma unroll
            for (int k = 0; k < 16; ++k) {
                float ev = sm[EHS_OFF + g * 16 + k];
                const float* wr = &sm[WHH_OFF + k * 512 + cg];
                zi += ev * wr[h];
                zf += ev * wr[16 + h];
                zg += ev * wr[32 + h];
                zo += ev * wr[48 + h];
            }
            float c2 = sigf(zf) * sm[ECS_OFF + g * 16 + h] + sigf(zi) * tanhf(zg);
            float hn = sigf(zo) * tanhf(c2);
            sm[RING_OFF + (g * 20 + s) * 144 + c * 16 + h] = hn;
            sm[NC_OFF + g * 128 + c * 16 + h] = c2;
        }
        __syncthreads();

        if (tid < 128) {
            // ================= small group: warps 0-3 =================
            // ---- GEMM-A: new-row slice (m=0) + old partial -> e1 ----
            {
                int jA = tid & 63, gp = tid >> 6;
                const float4* wA = reinterpret_cast<const float4*>(&sm[W1A_OFF]);
                const float4* r4 = reinterpret_cast<const float4*>(sm);
                int rb0 = ((2 * gp)     * 20 + s) * 36;
                int rb1 = ((2 * gp + 1) * 20 + s) * 36;
                float acc0 = 0.0f, acc1 = 0.0f;
                #pragma unroll 3
                for (int q = 0; q < 33; ++q) {
                    float4 w  = wA[q * 64 + jA];
                    float4 v0 = r4[rb0 + q];
                    acc0 += w.x * v0.x + w.y * v0.y + w.z * v0.z + w.w * v0.w;
                    float4 v1 = r4[rb1 + q];
                    acc1 += w.x * v1.x + w.y * v1.y + w.z * v1.z + w.w * v1.w;
                }
                int par = (t & 1) * 256;
                float bb = sm[B1S_OFF + jA];
                sm[E1S_OFF + (2 * gp) * 64 + jA] =
                    fmaxf(acc0 + sm[OLDPS_OFF + par + jA * 4 + 2 * gp] + bb, 0.0f);
                sm[E1S_OFF + (2 * gp + 1) * 64 + jA] =
                    fmaxf(acc1 + sm[OLDPS_OFF + par + jA * 4 + 2 * gp + 1] + bb, 0.0f);
            }
            asm volatile("bar.sync 1, 128;" ::: "memory");

            // ---- phase 5: MLP2 | expert heads | theta ----
            if (tid < 64) {
                int g = tid >> 4, j2 = tid & 15;
                float sacc = sm[B2S_OFF + j2];
                #pragma unroll
                for (int k = 0; k < 64; ++k)
                    sacc += sm[E1S_OFF + g * 64 + k] * sm[W2S_OFF + j2 * 65 + k];
                sm[AIS_OFF + g * 16 + j2] = fmaxf(sacc, 0.0f);
            } else if (tid < 96) {
                int u = tid - 64, g = u >> 3, c = u & 7;
                float sacc = sm[BOS_OFF + c];
                const float* rr = &sm[RING_OFF + (g * 20 + s) * 144 + c * 16];
                #pragma unroll
                for (int h = 0; h < 16; ++h) sacc += rr[h] * sm[WOS_OFF + c * 16 + h];
                sm[OSM_OFF + g * 8 + c] = sacc;
            } else if (tid < 100) {
                int g = tid - 96;
                float sacc = 0.0f;
                #pragma unroll
                for (int i2 = 0; i2 < 10; ++i2) sacc += fabsf(sm[ERRH_OFF + g * 10 + i2]);
                sm[THETA_OFF + g] = fminf(0.25f * sacc, 1.0f);
            }
            asm volatile("bar.sync 1, 128;" ::: "memory");

            // ---- phase 6: agent, 2 stacked LSTM layers ----
            #pragma unroll 1
            for (int l = 0; l < 2; ++l) {
                #pragma unroll
                for (int r = 0; r < 2; ++r) {
                    int e = tid + (r << 7);
                    int g = e >> 6, gate = e & 63;
                    const float* inp = (l == 0) ? &sm[AIS_OFF + g * 16]
                                                : &sm[AHS_OFF + g * 16];
                    const float* hp  = &sm[AHS_OFF + l * 64 + g * 16];
                    float z = sm[BAC_OFF + l * 64 + gate];
                    const float* wi = &sm[WAIH_OFF + l * 1024 + gate];
                    const float* wh = &sm[WAHH_OFF + l * 1024 + gate];
                    #pragma unroll
                    for (int k = 0; k < 16; ++k)
                        z += inp[k] * wi[k * 64] + hp[k] * wh[k * 64];
                    sm[ZBUF_OFF + g * 64 + gate] = z;
                }
                asm volatile("bar.sync 1, 128;" ::: "memory");
                if (tid < 64) {
                    int g2 = tid >> 4, h = tid & 15;
                    float zi = sm[ZBUF_OFF + g2 * 64 + h];
                    float zf = sm[ZBUF_OFF + g2 * 64 + 16 + h];
                    float zg = sm[ZBUF_OFF + g2 * 64 + 32 + h];
                    float zo = sm[ZBUF_OFF + g2 * 64 + 48 + h];
                    float c2 = sigf(zf) * sm[ACS_OFF + l * 64 + g2 * 16 + h]
                             + sigf(zi) * tanhf(zg);
                    float hn = sigf(zo) * tanhf(c2);
                    sm[ACS_OFF + l * 64 + g2 * 16 + h] = c2;
                    sm[AHS_OFF + l * 64 + g2 * 16 + h] = hn;
                }
                asm volatile("bar.sync 1, 128;" ::: "memory");
            }

            // ---- phase 7a: gate logits ----
            if (tid < 32) {
                int g = tid >> 3, c = tid & 7;
                float sacc = sm[BGS_OFF + c];
                const float* a1p = &sm[AHS_OFF + 64 + g * 16];
                #pragma unroll
                for (int k = 0; k < 16; ++k) sacc += a1p[k] * sm[WGS_OFF + c * 16 + k];
                sm[ZBUF_OFF + g * 8 + c] = sacc;
            }
            asm volatile("bar.sync 1, 128;" ::: "memory");

            // ---- phase 7b: softmax + blend + pred ----
            if (tid < 4) {
                int g = tid;
                float mx = -1e30f;
                #pragma unroll
                for (int c = 0; c < 8; ++c) mx = fmaxf(mx, sm[ZBUF_OFF + g * 8 + c]);
                float ex[8], ssum = 0.0f;
                #pragma unroll
                for (int c = 0; c < 8; ++c) { ex[c] = __expf(sm[ZBUF_OFF + g * 8 + c] - mx); ssum += ex[c]; }
                float inv = __fdividef(1.0f, ssum);
                float th = sm[THETA_OFF + g];
                float pred = 0.0f;
                #pragma unroll
                for (int c = 0; c < 8; ++c) {
                    float gf = ex[c] * inv * th + sm[GSM_OFF + g * 8 + c] * (1.0f - th);
                    sm[GSM_OFF + g * 8 + c] = gf;
                    pred += gf * sm[OSM_OFF + g * 8 + c];
                }
                sm[PRED_OFF + g] = pred;
                out[(b0 + g) * NSTEP + t] = pred;
            }
            asm volatile("bar.sync 1, 128;" ::: "memory");

            // ---- phase 7c: eh2 / ec2 ----
            if (tid < 64) {
                int g = tid >> 4, h = tid & 15;
                const float* rr = &sm[RING_OFF + (g * 20 + s) * 144];
                const float* nc = &sm[NC_OFF + g * 128];
                float se = 0.0f, sc = 0.0f;
                #pragma unroll
                for (int c = 0; c < 8; ++c) {
                    float gf = sm[GSM_OFF + g * 8 + c];
                    se += gf * rr[c * 16 + h];
                    sc += gf * nc[c * 16 + h];
                }
                sm[EHS_OFF + g * 16 + h] = se;
                sm[ECS_OFF + g * 16 + h] = sc;
            }
        } else {
            // ================= GEMM-B group: warps 4-15 (384 threads) =================
            // old-rows (m=1..19) partial for step t+1, fp16 weights, fp32 f32x2 accum
            const int u0 = tid - 128;
            const int cB = u0 >> 6;          // 0..5
            const int jB = u0 & 63;
            const int base = cB * 57;        // units in [0,342)
            int m0  = 1 + base / 18;
            int qq0 = base - (m0 - 1) * 18;
            int slot0 = (s + 19 + m0) % 20;  // (s-1+m0) mod 20
            int pos = slot0 * 18 + qq0;
            const uint4* wp = reinterpret_cast<const uint4*>(g_W1h) + (base + 18) * 64 + jB;
            const ulonglong2* ringU = reinterpret_cast<const ulonglong2*>(sm);

            unsigned long long aA0 = 0ull, aB0 = 0ull, aA1 = 0ull, aB1 = 0ull;
            unsigned long long aA2 = 0ull, aB2 = 0ull, aA3 = 0ull, aB3 = 0ull;

            #pragma unroll 3
            for (int it = 0; it < 57; ++it) {
                uint4 wv = *wp; wp += 64;
                unsigned long long w01 = f2ull(__half22float2(*reinterpret_cast<const __half2*>(&wv.x)));
                unsigned long long w23 = f2ull(__half22float2(*reinterpret_cast<const __half2*>(&wv.y)));
                unsigned long long w45 = f2ull(__half22float2(*reinterpret_cast<const __half2*>(&wv.z)));
                unsigned long long w67 = f2ull(__half22float2(*reinterpret_cast<const __half2*>(&wv.w)));
                int p2 = pos << 1;
                ulonglong2 rA = ringU[p2],        rB = ringU[p2 + 1];
                FMA2(aA0, w01, rA.x); FMA2(aB0, w23, rA.y);
                FMA2(aA0, w45, rB.x); FMA2(aB0, w67, rB.y);
                rA = ringU[720 + p2]; rB = ringU[720 + p2 + 1];
                FMA2(aA1, w01, rA.x); FMA2(aB1, w23, rA.y);
                FMA2(aA1, w45, rB.x); FMA2(aB1, w67, rB.y);
                rA = ringU[1440 + p2]; rB = ringU[1440 + p2 + 1];
                FMA2(aA2, w01, rA.x); FMA2(aB2, w23, rA.y);
                FMA2(aA2, w45, rB.x); FMA2(aB2, w67, rB.y);
                rA = ringU[2160 + p2]; rB = ringU[2160 + p2 + 1];
                FMA2(aA3, w01, rA.x); FMA2(aB3, w23, rA.y);
                FMA2(aA3, w45, rB.x); FMA2(aB3, w67, rB.y);
                ++pos; if (pos == 360) pos = 0;
            }
            float4* psb4 = reinterpret_cast<float4*>(&sm[PSB_OFF]);
            psb4[cB * 64 + jB] = make_float4(
                pair_sum(aA0) + pair_sum(aB0),
                pair_sum(aA1) + pair_sum(aB1),
                pair_sum(aA2) + pair_sum(aB2),
                pair_sum(aA3) + pair_sum(aB3));
            asm volatile("bar.sync 2, 384;" ::: "memory");
            if (tid < 384) {
                int r = tid - 128, jr = r & 63, gr = r >> 6;
                float sacc = 0.0f;
                #pragma unroll
                for (int c = 0; c < 6; ++c)
                    sacc += sm[PSB_OFF + (c * 64 + jr) * 4 + gr];
                sm[OLDPS_OFF + ((t + 1) & 1) * 256 + jr * 4 + gr] = sacc;
            }
        }
        __syncthreads();

        head = s;
    }
}

extern "C" void kernel_launch(void* const* d_in, const int* in_sizes, int n_in,
                              void* d_out, int out_size) {
    const float* x      = (const float*)d_in[0];
    const float* pred0  = (const float*)d_in[1];
    const float* gate0  = (const float*)d_in[2];
    const float* W_ih   = (const float*)d_in[3];
    const float* W_hh   = (const float*)d_in[4];
    const float* b_ih   = (const float*)d_in[5];
    const float* b_hh   = (const float*)d_in[6];
    const float* W_o    = (const float*)d_in[7];
    const float* b_o    = (const float*)d_in[8];
    const float* W1     = (const float*)d_in[9];
    const float* b1     = (const float*)d_in[10];
    const float* W2     = (const float*)d_in[11];
    const float* b2     = (const float*)d_in[12];
    const float* Wg     = (const float*)d_in[13];
    const float* bg     = (const float*)d_in[14];
    const float* Wa_ih  = (const float*)d_in[15];
    const float* Wa_hh  = (const float*)d_in[16];
    const float* ba_ih  = (const float*)d_in[17];
    const float* ba_hh  = (const float*)d_in[18];
    float* out = (float*)d_out;

    cudaFuncSetAttribute(mmoe_main, cudaFuncAttributeMaxDynamicSharedMemorySize, SMEM_BYTES);

    build_w1h<<<(W1H_ELEMS + 255) / 256, 256>>>(W1);
    mmoe_main<<<NCTA, NTHREADS, SMEM_BYTES>>>(
        x, pred0, gate0, W_ih, W_hh, b_ih, b_hh, W_o, b_o,
        W1, b1, W2, b2, Wg, bg, Wa_ih, Wa_hh, ba_ih, ba_hh, out);
}